// round 1
// baseline (speedup 1.0000x reference)
#include <cuda_runtime.h>
#include <math.h>

#define B_  8
#define S_  1024
#define D_  1024
#define H_  16
#define DK_ 64

// Scratch (device globals: no allocation allowed in kernel_launch)
__device__ float g_q[B_*S_*D_];
__device__ float g_k[B_*S_*D_];
__device__ float g_v[B_*S_*D_];
__device__ float g_att[B_*S_*D_];

// ---------------------------------------------------------------------------
// GEMM: C[M,N] = A[M,K] @ W[N,K]^T + bias[N]   (both operands K-major)
// 128x128x16 tile, 256 threads, 8x8 microtile.
// ---------------------------------------------------------------------------
__global__ void __launch_bounds__(256) gemm_bias_k(
    const float* __restrict__ A, const float* __restrict__ W,
    const float* __restrict__ bias, float* __restrict__ C,
    int M, int N, int K)
{
    __shared__ float As[16][128];
    __shared__ float Ws[16][128];
    const int tid = threadIdx.x;
    const int tx = tid & 15, ty = tid >> 4;
    const int m0 = blockIdx.y << 7, n0 = blockIdx.x << 7;

    float acc[8][8];
#pragma unroll
    for (int i = 0; i < 8; i++)
#pragma unroll
        for (int j = 0; j < 8; j++) acc[i][j] = 0.f;

    for (int k0 = 0; k0 < K; k0 += 16) {
#pragma unroll
        for (int l = 0; l < 2; l++) {
            const int f   = tid + (l << 8);
            const int row = f >> 2;
            const int kq  = (f & 3) << 2;
            const float4 av = *(const float4*)(A + (size_t)(m0 + row) * K + k0 + kq);
            As[kq+0][row] = av.x; As[kq+1][row] = av.y;
            As[kq+2][row] = av.z; As[kq+3][row] = av.w;
            const float4 wv = *(const float4*)(W + (size_t)(n0 + row) * K + k0 + kq);
            Ws[kq+0][row] = wv.x; Ws[kq+1][row] = wv.y;
            Ws[kq+2][row] = wv.z; Ws[kq+3][row] = wv.w;
        }
        __syncthreads();
#pragma unroll
        for (int kk = 0; kk < 16; kk++) {
            float a[8], b[8];
            *(float4*)&a[0] = *(float4*)&As[kk][ty * 8];
            *(float4*)&a[4] = *(float4*)&As[kk][ty * 8 + 4];
            *(float4*)&b[0] = *(float4*)&Ws[kk][tx * 8];
            *(float4*)&b[4] = *(float4*)&Ws[kk][tx * 8 + 4];
#pragma unroll
            for (int i = 0; i < 8; i++)
#pragma unroll
                for (int j = 0; j < 8; j++)
                    acc[i][j] += a[i] * b[j];
        }
        __syncthreads();
    }

#pragma unroll
    for (int i = 0; i < 8; i++) {
        const int row = m0 + ty * 8 + i;
#pragma unroll
        for (int j0 = 0; j0 < 8; j0 += 4) {
            const int col = n0 + tx * 8 + j0;
            float4 r;
            r.x = acc[i][j0+0] + bias[col+0];
            r.y = acc[i][j0+1] + bias[col+1];
            r.z = acc[i][j0+2] + bias[col+2];
            r.w = acc[i][j0+3] + bias[col+3];
            *(float4*)(C + (size_t)row * N + col) = r;
        }
    }
}

// ---------------------------------------------------------------------------
// Flash attention (fp32): per block one (b, h, 64-row q-tile).
// 256 threads as 16x16; each thread a 4x4 microtile of S and of O.
// Smem tiles XOR-swizzled at 16B-chunk granularity for conflict-free .128.
// ---------------------------------------------------------------------------
__global__ void __launch_bounds__(256) flash_k(
    const float* __restrict__ Q, const float* __restrict__ Kp,
    const float* __restrict__ V, const int* __restrict__ mask,
    float* __restrict__ O)
{
    extern __shared__ float sm[];
    float* Qs = sm;          // [64][64]
    float* Ks = sm + 4096;   // [64][64] swizzled
    float* Vs = sm + 8192;   // [64][64] swizzled
    float* Ps = sm + 12288;  // [64][64] (Ps[j][i]) swizzled

    const int tid = threadIdx.x;
    const int tx = tid & 15, ty = tid >> 4;
    const int q0 = (int)blockIdx.x << 6;
    const int bh = blockIdx.y;
    const int b  = bh >> 4, h = bh & 15;
    const int xt = tx & 7;   // swizzle key for own k-column rows (j>>2 == tx)
    const float sc = 0.125f; // 1/sqrt(64)

    // Load Q tile [64 q-rows][64 dims], natural layout
#pragma unroll
    for (int l = 0; l < 4; l++) {
        const int f = tid + (l << 8);
        const int i = f >> 4, cc = f & 15;
        *(float4*)&Qs[i * 64 + cc * 4] =
            *(const float4*)(Q + (size_t)(b * S_ + q0 + i) * D_ + h * DK_ + cc * 4);
    }

    float m_r[4], l_r[4], o[4][4];
#pragma unroll
    for (int ii = 0; ii < 4; ii++) {
        m_r[ii] = -INFINITY; l_r[ii] = 0.f;
#pragma unroll
        for (int dd = 0; dd < 4; dd++) o[ii][dd] = 0.f;
    }

    for (int kt = 0; kt < S_ / 64; kt++) {
        const int k0 = kt << 6;
        __syncthreads();  // prior AV reads of Vs/Ps done before overwrite
#pragma unroll
        for (int l = 0; l < 4; l++) {
            const int f = tid + (l << 8);
            const int j = f >> 4, cc = f & 15;
            const int ccs = cc ^ ((j >> 2) & 7);
            const size_t src = (size_t)(b * S_ + k0 + j) * D_ + h * DK_ + cc * 4;
            *(float4*)&Ks[j * 64 + ccs * 4] = *(const float4*)(Kp + src);
            *(float4*)&Vs[j * 64 + ccs * 4] = *(const float4*)(V + src);
        }
        __syncthreads();

        // S = Q K^T  (4x4 microtile per thread)
        float s[4][4];
#pragma unroll
        for (int ii = 0; ii < 4; ii++)
#pragma unroll
            for (int jj = 0; jj < 4; jj++) s[ii][jj] = 0.f;

#pragma unroll
        for (int dc = 0; dc < 16; dc++) {
            float4 q4[4], k4[4];
#pragma unroll
            for (int ii = 0; ii < 4; ii++)
                q4[ii] = *(float4*)&Qs[(ty * 4 + ii) * 64 + dc * 4];
#pragma unroll
            for (int jj = 0; jj < 4; jj++)
                k4[jj] = *(float4*)&Ks[(tx * 4 + jj) * 64 + ((dc ^ xt) << 2)];
#pragma unroll
            for (int ii = 0; ii < 4; ii++)
#pragma unroll
                for (int jj = 0; jj < 4; jj++) {
                    s[ii][jj] += q4[ii].x * k4[jj].x;
                    s[ii][jj] += q4[ii].y * k4[jj].y;
                    s[ii][jj] += q4[ii].z * k4[jj].z;
                    s[ii][jj] += q4[ii].w * k4[jj].w;
                }
        }

        // Mask + online softmax, per q-row (rows ty*4+ii; 16 lanes per row group)
#pragma unroll
        for (int ii = 0; ii < 4; ii++) {
            const int4 mk = *(const int4*)(
                mask + (size_t)(b * S_ + q0 + ty * 4 + ii) * S_ + k0 + tx * 4);
            s[ii][0] = mk.x ? s[ii][0] * sc : -INFINITY;
            s[ii][1] = mk.y ? s[ii][1] * sc : -INFINITY;
            s[ii][2] = mk.z ? s[ii][2] * sc : -INFINITY;
            s[ii][3] = mk.w ? s[ii][3] * sc : -INFINITY;

            float mt = fmaxf(fmaxf(s[ii][0], s[ii][1]), fmaxf(s[ii][2], s[ii][3]));
            mt = fmaxf(mt, __shfl_xor_sync(0xffffffffu, mt, 1));
            mt = fmaxf(mt, __shfl_xor_sync(0xffffffffu, mt, 2));
            mt = fmaxf(mt, __shfl_xor_sync(0xffffffffu, mt, 4));
            mt = fmaxf(mt, __shfl_xor_sync(0xffffffffu, mt, 8));
            const float mn = fmaxf(m_r[ii], mt);

            float p0, p1, p2, p3, alpha;
            if (mn == -INFINITY) {   // fully masked so far: keep state
                p0 = p1 = p2 = p3 = 0.f; alpha = 1.f;
            } else {
                alpha = __expf(m_r[ii] - mn);    // m_r = -inf -> 0, OK
                p0 = __expf(s[ii][0] - mn);
                p1 = __expf(s[ii][1] - mn);
                p2 = __expf(s[ii][2] - mn);
                p3 = __expf(s[ii][3] - mn);
            }
            float rs = p0 + p1 + p2 + p3;
            rs += __shfl_xor_sync(0xffffffffu, rs, 1);
            rs += __shfl_xor_sync(0xffffffffu, rs, 2);
            rs += __shfl_xor_sync(0xffffffffu, rs, 4);
            rs += __shfl_xor_sync(0xffffffffu, rs, 8);

            l_r[ii] = alpha * l_r[ii] + rs;
            m_r[ii] = mn;
            o[ii][0] *= alpha; o[ii][1] *= alpha;
            o[ii][2] *= alpha; o[ii][3] *= alpha;

            // Store P transposed: Ps[j][i], chunk cc = i>>2 = ty, swizzled by row j
            const int swz = ((ty ^ xt) << 2) + ii;
            Ps[(tx * 4 + 0) * 64 + swz] = p0;
            Ps[(tx * 4 + 1) * 64 + swz] = p1;
            Ps[(tx * 4 + 2) * 64 + swz] = p2;
            Ps[(tx * 4 + 3) * 64 + swz] = p3;
        }
        __syncthreads();

        // O += P V   (rows i = ty*4+ii, dims d = tx*4+dd)
#pragma unroll
        for (int j = 0; j < 64; j++) {
            const int xj = (j >> 2) & 7;
            const float4 p4 = *(float4*)&Ps[j * 64 + ((ty ^ xj) << 2)];
            const float4 v4 = *(float4*)&Vs[j * 64 + ((tx ^ xj) << 2)];
            o[0][0] += p4.x * v4.x; o[0][1] += p4.x * v4.y;
            o[0][2] += p4.x * v4.z; o[0][3] += p4.x * v4.w;
            o[1][0] += p4.y * v4.x; o[1][1] += p4.y * v4.y;
            o[1][2] += p4.y * v4.z; o[1][3] += p4.y * v4.w;
            o[2][0] += p4.z * v4.x; o[2][1] += p4.z * v4.y;
            o[2][2] += p4.z * v4.z; o[2][3] += p4.z * v4.w;
            o[3][0] += p4.w * v4.x; o[3][1] += p4.w * v4.y;
            o[3][2] += p4.w * v4.z; o[3][3] += p4.w * v4.w;
        }
    }

    // Normalize and write out to [B,S,H*DK] layout (ready for output proj)
#pragma unroll
    for (int ii = 0; ii < 4; ii++) {
        const float inv = (l_r[ii] > 0.f) ? (1.0f / l_r[ii]) : 0.f;
        float4 r;
        r.x = o[ii][0] * inv; r.y = o[ii][1] * inv;
        r.z = o[ii][2] * inv; r.w = o[ii][3] * inv;
        *(float4*)(O + (size_t)(b * S_ + q0 + ty * 4 + ii) * D_ + h * DK_ + tx * 4) = r;
    }
}

// ---------------------------------------------------------------------------
extern "C" void kernel_launch(void* const* d_in, const int* in_sizes, int n_in,
                              void* d_out, int out_size) {
    (void)in_sizes; (void)n_in; (void)out_size;
    const float* query = (const float*)d_in[0];
    const float* key   = (const float*)d_in[1];
    const float* value = (const float*)d_in[2];
    const int*   msk   = (const int*)  d_in[3];
    const float* wq = (const float*)d_in[4];  const float* bq = (const float*)d_in[5];
    const float* wk = (const float*)d_in[6];  const float* bk = (const float*)d_in[7];
    const float* wv = (const float*)d_in[8];  const float* bv = (const float*)d_in[9];
    const float* wo = (const float*)d_in[10]; const float* bo = (const float*)d_in[11];
    float* out = (float*)d_out;

    float *gq, *gk, *gv, *ga;
    cudaGetSymbolAddress((void**)&gq, g_q);
    cudaGetSymbolAddress((void**)&gk, g_k);
    cudaGetSymbolAddress((void**)&gv, g_v);
    cudaGetSymbolAddress((void**)&ga, g_att);

    const int M = B_ * S_;
    const dim3 gGrid(D_ / 128, M / 128);

    gemm_bias_k<<<gGrid, 256>>>(query, wq, bq, gq, M, D_, D_);
    gemm_bias_k<<<gGrid, 256>>>(key,   wk, bk, gk, M, D_, D_);
    gemm_bias_k<<<gGrid, 256>>>(value, wv, bv, gv, M, D_, D_);

    static bool attr_set = false;
    if (!attr_set) {
        cudaFuncSetAttribute(flash_k, cudaFuncAttributeMaxDynamicSharedMemorySize, 65536);
        attr_set = true;
    }
    flash_k<<<dim3(S_ / 64, B_ * H_), 256, 65536>>>(gq, gk, gv, msk, ga);

    gemm_bias_k<<<gGrid, 256>>>(ga, wo, bo, out, M, D_, D_);
}

// round 3
// speedup vs baseline: 1.8580x; 1.8580x over previous
#include <cuda_runtime.h>
#include <math.h>

#define B_  8
#define S_  1024
#define D_  1024
#define H_  16
#define DK_ 64

// Scratch (device globals: no allocation allowed in kernel_launch)
__device__ float g_q[B_*S_*D_];
__device__ float g_k[B_*S_*D_];
__device__ float g_v[B_*S_*D_];
__device__ float g_att[B_*S_*D_];

// ---------------------------------------------------------------------------
// tf32 tensor-core GEMM: C[M,N] = A[M,K] @ W[N,K]^T + bias[N]
// 128x128x32 CTA tile, 256 threads = 8 warps (2 M x 4 N), warp tile 64x32.
// mma.sync.m16n8k8 tf32, cp.async double-buffered, smem stride 36 (pad 4)
// => conflict-free LDS.32 fragment loads. cvt.rna at fragment load for
// unbiased tf32 rounding (truncation bias over K=1024 would exceed 1e-3).
// ---------------------------------------------------------------------------
#define TILE_F 4608   // 128*36 floats per smem tile

__device__ __forceinline__ unsigned f2tf32(float x) {
    unsigned u;
    asm("cvt.rna.tf32.f32 %0, %1;" : "=r"(u) : "f"(x));
    return u;
}

__global__ void __launch_bounds__(256) gemm_tf32(
    const float* __restrict__ A, const float* __restrict__ W,
    const float* __restrict__ bias, float* __restrict__ C,
    int M, int N, int K)
{
    extern __shared__ float sm[];
    // layout: [stage][A tile | W tile]
    const int tid  = threadIdx.x;
    const int warp = tid >> 5, lane = tid & 31;
    const int wm = warp & 1, wn = warp >> 1;       // 2 x 4 warp grid
    const int g = lane >> 2, t = lane & 3;
    const int m0 = blockIdx.y << 7, n0 = blockIdx.x << 7;

    const int lrow = tid >> 3;          // 0..31
    const int lcol = (tid & 7) << 2;    // 0,4,..28

    float acc[4][4][4];
#pragma unroll
    for (int i = 0; i < 4; i++)
#pragma unroll
        for (int j = 0; j < 4; j++)
#pragma unroll
            for (int c = 0; c < 4; c++) acc[i][j][c] = 0.f;

    const int NCHUNK = K >> 5;

    // prefetch chunk 0 into stage 0
    {
        float* sA = sm;
        float* sW = sm + TILE_F;
#pragma unroll
        for (int l = 0; l < 4; l++) {
            const int row = lrow + (l << 5);
            unsigned da = (unsigned)__cvta_generic_to_shared(&sA[row * 36 + lcol]);
            unsigned dw = (unsigned)__cvta_generic_to_shared(&sW[row * 36 + lcol]);
            const float* ga = A + (size_t)(m0 + row) * K + lcol;
            const float* gw = W + (size_t)(n0 + row) * K + lcol;
            asm volatile("cp.async.cg.shared.global [%0], [%1], 16;" :: "r"(da), "l"(ga));
            asm volatile("cp.async.cg.shared.global [%0], [%1], 16;" :: "r"(dw), "l"(gw));
        }
        asm volatile("cp.async.commit_group;");
    }

    for (int kc = 0; kc < NCHUNK; kc++) {
        if (kc + 1 < NCHUNK) {
            const int k0 = (kc + 1) << 5;
            float* sA = sm + ((kc + 1) & 1) * (2 * TILE_F);
            float* sW = sA + TILE_F;
#pragma unroll
            for (int l = 0; l < 4; l++) {
                const int row = lrow + (l << 5);
                unsigned da = (unsigned)__cvta_generic_to_shared(&sA[row * 36 + lcol]);
                unsigned dw = (unsigned)__cvta_generic_to_shared(&sW[row * 36 + lcol]);
                const float* ga = A + (size_t)(m0 + row) * K + k0 + lcol;
                const float* gw = W + (size_t)(n0 + row) * K + k0 + lcol;
                asm volatile("cp.async.cg.shared.global [%0], [%1], 16;" :: "r"(da), "l"(ga));
                asm volatile("cp.async.cg.shared.global [%0], [%1], 16;" :: "r"(dw), "l"(gw));
            }
            asm volatile("cp.async.commit_group;");
            asm volatile("cp.async.wait_group 1;");
        } else {
            asm volatile("cp.async.wait_group 0;");
        }
        __syncthreads();

        const float* sA = sm + (kc & 1) * (2 * TILE_F);
        const float* sW = sA + TILE_F;

#pragma unroll
        for (int ks = 0; ks < 4; ks++) {
            const int kk = ks << 3;
            unsigned af[4][4], bf[4][2];
#pragma unroll
            for (int ma = 0; ma < 4; ma++) {
                const int r0 = wm * 64 + ma * 16 + g;
                af[ma][0] = f2tf32(sA[r0 * 36 + kk + t]);
                af[ma][1] = f2tf32(sA[(r0 + 8) * 36 + kk + t]);
                af[ma][2] = f2tf32(sA[r0 * 36 + kk + t + 4]);
                af[ma][3] = f2tf32(sA[(r0 + 8) * 36 + kk + t + 4]);
            }
#pragma unroll
            for (int na = 0; na < 4; na++) {
                const int rn = wn * 32 + na * 8 + g;
                bf[na][0] = f2tf32(sW[rn * 36 + kk + t]);
                bf[na][1] = f2tf32(sW[rn * 36 + kk + t + 4]);
            }
#pragma unroll
            for (int ma = 0; ma < 4; ma++)
#pragma unroll
                for (int na = 0; na < 4; na++) {
                    asm volatile(
                        "mma.sync.aligned.m16n8k8.row.col.f32.tf32.tf32.f32 "
                        "{%0,%1,%2,%3}, {%4,%5,%6,%7}, {%8,%9}, {%0,%1,%2,%3};"
                        : "+f"(acc[ma][na][0]), "+f"(acc[ma][na][1]),
                          "+f"(acc[ma][na][2]), "+f"(acc[ma][na][3])
                        : "r"(af[ma][0]), "r"(af[ma][1]), "r"(af[ma][2]), "r"(af[ma][3]),
                          "r"(bf[na][0]), "r"(bf[na][1]));
                }
        }
        __syncthreads();
    }

    // epilogue: bias + store (c0,c1 contiguous cols -> float2 stores)
#pragma unroll
    for (int na = 0; na < 4; na++) {
        const int col = n0 + wn * 32 + na * 8 + 2 * t;
        const float bx = bias[col], by = bias[col + 1];
#pragma unroll
        for (int ma = 0; ma < 4; ma++) {
            const int row0 = m0 + wm * 64 + ma * 16 + g;
            float2 r;
            r.x = acc[ma][na][0] + bx; r.y = acc[ma][na][1] + by;
            *(float2*)(C + (size_t)row0 * N + col) = r;
            r.x = acc[ma][na][2] + bx; r.y = acc[ma][na][3] + by;
            *(float2*)(C + (size_t)(row0 + 8) * N + col) = r;
        }
    }
}

// ---------------------------------------------------------------------------
// Flash attention (fp32): per block one (b, h, 64-row q-tile).
// 256 threads as 16x16; each thread a 4x4 microtile of S and of O.
// ---------------------------------------------------------------------------
__global__ void __launch_bounds__(256) flash_k(
    const float* __restrict__ Q, const float* __restrict__ Kp,
    const float* __restrict__ V, const int* __restrict__ mask,
    float* __restrict__ O)
{
    extern __shared__ float smf[];
    float* Qs = smf;          // [64][64]
    float* Ks = smf + 4096;   // [64][64] swizzled
    float* Vs = smf + 8192;   // [64][64] swizzled
    float* Ps = smf + 12288;  // [64][64] (Ps[j][i]) swizzled

    const int tid = threadIdx.x;
    const int tx = tid & 15, ty = tid >> 4;
    const int q0 = (int)blockIdx.x << 6;
    const int bh = blockIdx.y;
    const int b  = bh >> 4, h = bh & 15;
    const int xt = tx & 7;
    const float sc = 0.125f;

#pragma unroll
    for (int l = 0; l < 4; l++) {
        const int f = tid + (l << 8);
        const int i = f >> 4, cc = f & 15;
        *(float4*)&Qs[i * 64 + cc * 4] =
            *(const float4*)(Q + (size_t)(b * S_ + q0 + i) * D_ + h * DK_ + cc * 4);
    }

    float m_r[4], l_r[4], o[4][4];
#pragma unroll
    for (int ii = 0; ii < 4; ii++) {
        m_r[ii] = -INFINITY; l_r[ii] = 0.f;
#pragma unroll
        for (int dd = 0; dd < 4; dd++) o[ii][dd] = 0.f;
    }

    for (int kt = 0; kt < S_ / 64; kt++) {
        const int k0 = kt << 6;
        __syncthreads();
#pragma unroll
        for (int l = 0; l < 4; l++) {
            const int f = tid + (l << 8);
            const int j = f >> 4, cc = f & 15;
            const int ccs = cc ^ ((j >> 2) & 7);
            const size_t src = (size_t)(b * S_ + k0 + j) * D_ + h * DK_ + cc * 4;
            *(float4*)&Ks[j * 64 + ccs * 4] = *(const float4*)(Kp + src);
            *(float4*)&Vs[j * 64 + ccs * 4] = *(const float4*)(V + src);
        }
        __syncthreads();

        float s[4][4];
#pragma unroll
        for (int ii = 0; ii < 4; ii++)
#pragma unroll
            for (int jj = 0; jj < 4; jj++) s[ii][jj] = 0.f;

#pragma unroll
        for (int dc = 0; dc < 16; dc++) {
            float4 q4[4], k4[4];
#pragma unroll
            for (int ii = 0; ii < 4; ii++)
                q4[ii] = *(float4*)&Qs[(ty * 4 + ii) * 64 + dc * 4];
#pragma unroll
            for (int jj = 0; jj < 4; jj++)
                k4[jj] = *(float4*)&Ks[(tx * 4 + jj) * 64 + ((dc ^ xt) << 2)];
#pragma unroll
            for (int ii = 0; ii < 4; ii++)
#pragma unroll
                for (int jj = 0; jj < 4; jj++) {
                    s[ii][jj] += q4[ii].x * k4[jj].x;
                    s[ii][jj] += q4[ii].y * k4[jj].y;
                    s[ii][jj] += q4[ii].z * k4[jj].z;
                    s[ii][jj] += q4[ii].w * k4[jj].w;
                }
        }

#pragma unroll
        for (int ii = 0; ii < 4; ii++) {
            const int4 mk = *(const int4*)(
                mask + (size_t)(b * S_ + q0 + ty * 4 + ii) * S_ + k0 + tx * 4);
            s[ii][0] = mk.x ? s[ii][0] * sc : -INFINITY;
            s[ii][1] = mk.y ? s[ii][1] * sc : -INFINITY;
            s[ii][2] = mk.z ? s[ii][2] * sc : -INFINITY;
            s[ii][3] = mk.w ? s[ii][3] * sc : -INFINITY;

            float mt = fmaxf(fmaxf(s[ii][0], s[ii][1]), fmaxf(s[ii][2], s[ii][3]));
            mt = fmaxf(mt, __shfl_xor_sync(0xffffffffu, mt, 1));
            mt = fmaxf(mt, __shfl_xor_sync(0xffffffffu, mt, 2));
            mt = fmaxf(mt, __shfl_xor_sync(0xffffffffu, mt, 4));
            mt = fmaxf(mt, __shfl_xor_sync(0xffffffffu, mt, 8));
            const float mn = fmaxf(m_r[ii], mt);

            float p0, p1, p2, p3, alpha;
            if (mn == -INFINITY) {
                p0 = p1 = p2 = p3 = 0.f; alpha = 1.f;
            } else {
                alpha = __expf(m_r[ii] - mn);
                p0 = __expf(s[ii][0] - mn);
                p1 = __expf(s[ii][1] - mn);
                p2 = __expf(s[ii][2] - mn);
                p3 = __expf(s[ii][3] - mn);
            }
            float rs = p0 + p1 + p2 + p3;
            rs += __shfl_xor_sync(0xffffffffu, rs, 1);
            rs += __shfl_xor_sync(0xffffffffu, rs, 2);
            rs += __shfl_xor_sync(0xffffffffu, rs, 4);
            rs += __shfl_xor_sync(0xffffffffu, rs, 8);

            l_r[ii] = alpha * l_r[ii] + rs;
            m_r[ii] = mn;
            o[ii][0] *= alpha; o[ii][1] *= alpha;
            o[ii][2] *= alpha; o[ii][3] *= alpha;

            const int swz = ((ty ^ xt) << 2) + ii;
            Ps[(tx * 4 + 0) * 64 + swz] = p0;
            Ps[(tx * 4 + 1) * 64 + swz] = p1;
            Ps[(tx * 4 + 2) * 64 + swz] = p2;
            Ps[(tx * 4 + 3) * 64 + swz] = p3;
        }
        __syncthreads();

#pragma unroll
        for (int j = 0; j < 64; j++) {
            const int xj = (j >> 2) & 7;
            const float4 p4 = *(float4*)&Ps[j * 64 + ((ty ^ xj) << 2)];
            const float4 v4 = *(float4*)&Vs[j * 64 + ((tx ^ xj) << 2)];
            o[0][0] += p4.x * v4.x; o[0][1] += p4.x * v4.y;
            o[0][2] += p4.x * v4.z; o[0][3] += p4.x * v4.w;
            o[1][0] += p4.y * v4.x; o[1][1] += p4.y * v4.y;
            o[1][2] += p4.y * v4.z; o[1][3] += p4.y * v4.w;
            o[2][0] += p4.z * v4.x; o[2][1] += p4.z * v4.y;
            o[2][2] += p4.z * v4.z; o[2][3] += p4.z * v4.w;
            o[3][0] += p4.w * v4.x; o[3][1] += p4.w * v4.y;
            o[3][2] += p4.w * v4.z; o[3][3] += p4.w * v4.w;
        }
    }

#pragma unroll
    for (int ii = 0; ii < 4; ii++) {
        const float inv = (l_r[ii] > 0.f) ? (1.0f / l_r[ii]) : 0.f;
        float4 r;
        r.x = o[ii][0] * inv; r.y = o[ii][1] * inv;
        r.z = o[ii][2] * inv; r.w = o[ii][3] * inv;
        *(float4*)(O + (size_t)(b * S_ + q0 + ty * 4 + ii) * D_ + h * DK_ + tx * 4) = r;
    }
}

// ---------------------------------------------------------------------------
extern "C" void kernel_launch(void* const* d_in, const int* in_sizes, int n_in,
                              void* d_out, int out_size) {
    (void)in_sizes; (void)n_in; (void)out_size;
    const float* query = (const float*)d_in[0];
    const float* key   = (const float*)d_in[1];
    const float* value = (const float*)d_in[2];
    const int*   msk   = (const int*)  d_in[3];
    const float* wq = (const float*)d_in[4];  const float* bq = (const float*)d_in[5];
    const float* wk = (const float*)d_in[6];  const float* bk = (const float*)d_in[7];
    const float* wv = (const float*)d_in[8];  const float* bv = (const float*)d_in[9];
    const float* wo = (const float*)d_in[10]; const float* bo = (const float*)d_in[11];
    float* out = (float*)d_out;

    float *gq, *gk, *gv, *ga;
    cudaGetSymbolAddress((void**)&gq, g_q);
    cudaGetSymbolAddress((void**)&gk, g_k);
    cudaGetSymbolAddress((void**)&gv, g_v);
    cudaGetSymbolAddress((void**)&ga, g_att);

    const int M = B_ * S_;
    const dim3 gGrid(D_ / 128, M / 128);
    const int gemm_smem = 4 * TILE_F * sizeof(float);  // 73728 B

    static bool attr_set = false;
    if (!attr_set) {
        cudaFuncSetAttribute(gemm_tf32, cudaFuncAttributeMaxDynamicSharedMemorySize, gemm_smem);
        cudaFuncSetAttribute(flash_k, cudaFuncAttributeMaxDynamicSharedMemorySize, 65536);
        attr_set = true;
    }

    gemm_tf32<<<gGrid, 256, gemm_smem>>>(query, wq, bq, gq, M, D_, D_);
    gemm_tf32<<<gGrid, 256, gemm_smem>>>(key,   wk, bk, gk, M, D_, D_);
    gemm_tf32<<<gGrid, 256, gemm_smem>>>(value, wv, bv, gv, M, D_, D_);

    flash_k<<<dim3(S_ / 64, B_ * H_), 256, 65536>>>(gq, gk, gv, msk, ga);

    gemm_tf32<<<gGrid, 256, gemm_smem>>>(ga, wo, bo, out, M, D_, D_);
}